// round 2
// baseline (speedup 1.0000x reference)
#include <cuda_runtime.h>
#include <cuda_bf16.h>

// ---------------------------------------------------------------------------
// Problem constants
//   B=128, T=32, N=196, E=FD=H=A=1024, 4H=4096, E+FD=2048
// Inputs (metadata order):
//   0 feats[128,196,1024] 1 embeddings[128,32,1024] 2 Wf[1024,1024] 3 Wh[1024,1024]
//   4 b_att[1024] 5 v[1024] 6 W_ih0[4096,2048] 7 W_hh0[4096,1024]
//   8 b_ih0[4096] 9 b_hh0[4096] 10 W_ih1[4096,1024] 11 W_hh1[4096,1024]
//   12 b_ih1[4096] 13 b_hh1[4096]
// Output: [128,32,1024] fp32
// ---------------------------------------------------------------------------

#define ULL unsigned long long

// ------------------------------ scratch ------------------------------------
__device__ float g_fproj[25088 * 1024];      // [b][n][a]          102.8 MB
__device__ float g_pre0[32 * 128 * 4096];    // [t][b][j]           67.1 MB
__device__ float g_w1c[4096 * 1024];         // W_ih1 + W_hh1       16.8 MB
__device__ float g_b0c[4096];
__device__ float g_b1c[4096];
__device__ float g_h0[128 * 1024];
__device__ float g_c0[128 * 1024];
__device__ float g_q[128 * 1024];
__device__ float g_scores[128 * 196];
__device__ float g_attn[128 * 1024];
__device__ float g_gates[128 * 4096];
__device__ float g_h0all[32 * 128 * 1024];   // [t][b][h]
__device__ float g_c0all[32 * 128 * 1024];
__device__ float g_gates1[32 * 128 * 4096];  // 67.1 MB

// ------------------------------ helpers ------------------------------------
__device__ __forceinline__ ULL pack2(float x, float y) {
    ULL r; asm("mov.b64 %0, {%1, %2};" : "=l"(r) : "f"(x), "f"(y)); return r;
}
__device__ __forceinline__ float2 unpack2(ULL v) {
    float2 r; asm("mov.b64 {%0, %1}, %2;" : "=f"(r.x), "=f"(r.y) : "l"(v)); return r;
}
__device__ __forceinline__ void fma2(ULL& d, ULL a, ULL b) {
    asm("fma.rn.f32x2 %0, %1, %2, %0;" : "+l"(d) : "l"(a), "l"(b));
}
__device__ __forceinline__ float fast_tanh(float x) {
    float r; asm("tanh.approx.f32 %0, %1;" : "=f"(r) : "f"(x)); return r;
}
__device__ __forceinline__ float sigf(float x) { return 1.f / (1.f + __expf(-x)); }

// ---------------------------------------------------------------------------
// Generic tiled GEMM:  C[M,N] = A[M,K] * op(B) (+bias)
//   BT=false: B is [K,N] row-major (C = A*B)
//   BT=true : B is [N,K] row-major (C = A*B^T)
//   PERM    : A row index m maps to source row (m%128)*32 + m/128   (pre0)
//   ATOMIC  : atomicAdd into C (for split-K); else store (+bias if BIAS)
// Block tile 128x128, BK=8, 256 threads, 8x8 per-thread, f32x2 FMAs.
// M % 128 == 0, N % 128 == 0, kLen % 8 == 0 required.
// grid = (M/128, N/128, kSplit)
// ---------------------------------------------------------------------------
template <bool BT, bool PERM, bool ATOMIC, bool BIAS>
__global__ __launch_bounds__(256) void gemm128_kernel(
    const float* __restrict__ A, int lda,
    const float* __restrict__ B, int ldb,
    float* __restrict__ C, int ldc,
    const float* __restrict__ bias,
    int K, int kLen)
{
    __shared__ __align__(16) float As[8][128];
    __shared__ __align__(16) float Bs[8][128];

    const int tid = threadIdx.x;
    const int m0 = blockIdx.x * 128;
    const int n0 = blockIdx.y * 128;
    const int kBeg = blockIdx.z * kLen;

    const int tx = tid & 15;   // n-group: 8 cols
    const int ty = tid >> 4;   // m-group: 8 rows

    ULL acc[8][4];
#pragma unroll
    for (int i = 0; i < 8; i++)
#pragma unroll
        for (int j = 0; j < 4; j++) acc[i][j] = 0ull;

    const int arow = tid >> 1, akq = tid & 1;
    int ar = m0 + arow;
    if (PERM) ar = (ar & 127) * 32 + (ar >> 7);
    const float* Aptr = A + (long)ar * lda + akq * 4;

    const float* Bptr;
    if (BT) {
        Bptr = B + (long)(n0 + (tid >> 1)) * ldb + (tid & 1) * 4;
    } else {
        Bptr = B + (long)(tid >> 5) * ldb + n0 + (tid & 31) * 4;
    }

    for (int kt = kBeg; kt < kBeg + kLen; kt += 8) {
        float4 a4 = *(const float4*)(Aptr + kt);
        As[akq * 4 + 0][arow] = a4.x;
        As[akq * 4 + 1][arow] = a4.y;
        As[akq * 4 + 2][arow] = a4.z;
        As[akq * 4 + 3][arow] = a4.w;
        if (BT) {
            float4 b4 = *(const float4*)(Bptr + kt);
            const int brow = tid >> 1, bkq = tid & 1;
            Bs[bkq * 4 + 0][brow] = b4.x;
            Bs[bkq * 4 + 1][brow] = b4.y;
            Bs[bkq * 4 + 2][brow] = b4.z;
            Bs[bkq * 4 + 3][brow] = b4.w;
        } else {
            float4 b4 = *(const float4*)(Bptr + (long)kt * ldb);
            *(float4*)&Bs[tid >> 5][(tid & 31) * 4] = b4;
        }
        __syncthreads();
#pragma unroll
        for (int kk = 0; kk < 8; kk++) {
            float4 aA = *(const float4*)&As[kk][ty * 8];
            float4 aB = *(const float4*)&As[kk][ty * 8 + 4];
            ulonglong2 b0 = *(const ulonglong2*)&Bs[kk][tx * 8];
            ulonglong2 b1 = *(const ulonglong2*)&Bs[kk][tx * 8 + 4];
            ULL ap[8];
            ap[0] = pack2(aA.x, aA.x); ap[1] = pack2(aA.y, aA.y);
            ap[2] = pack2(aA.z, aA.z); ap[3] = pack2(aA.w, aA.w);
            ap[4] = pack2(aB.x, aB.x); ap[5] = pack2(aB.y, aB.y);
            ap[6] = pack2(aB.z, aB.z); ap[7] = pack2(aB.w, aB.w);
#pragma unroll
            for (int i = 0; i < 8; i++) {
                fma2(acc[i][0], ap[i], b0.x);
                fma2(acc[i][1], ap[i], b0.y);
                fma2(acc[i][2], ap[i], b1.x);
                fma2(acc[i][3], ap[i], b1.y);
            }
        }
        __syncthreads();
    }

#pragma unroll
    for (int i = 0; i < 8; i++) {
        float* Crow = C + (long)(m0 + ty * 8 + i) * ldc + n0 + tx * 8;
#pragma unroll
        for (int j = 0; j < 4; j++) {
            float2 vv = unpack2(acc[i][j]);
            if (ATOMIC) {
                atomicAdd(&Crow[j * 2], vv.x);
                atomicAdd(&Crow[j * 2 + 1], vv.y);
            } else {
                if (BIAS) {
                    vv.x += bias[n0 + tx * 8 + j * 2];
                    vv.y += bias[n0 + tx * 8 + j * 2 + 1];
                }
                Crow[j * 2] = vv.x;
                Crow[j * 2 + 1] = vv.y;
            }
        }
    }
}

// ---------------------------------------------------------------------------
// gates0 = pre0_t + attn @ W_ih0[:,1024:]^T + h0 @ W_hh0^T
// g_gates pre-initialized (D2D copy of pre0 slice); blocks atomicAdd partials.
// grid (64, 1, 4): x = N-tile (BN=64), z = (ksplit<<1)|gemm_id. BM=128, BK=8.
// 256 threads, per-thread 4x8, f32x2.
// ---------------------------------------------------------------------------
__global__ __launch_bounds__(256) void gates_kernel(
    const float* __restrict__ W_ih0, const float* __restrict__ W_hh0)
{
    __shared__ __align__(16) float As[8][128];
    __shared__ __align__(16) float Bs[8][64];

    const int tid = threadIdx.x;
    const int z = blockIdx.z;
    const int gsel = z & 1, kh = z >> 1;
    const float* X = gsel ? g_h0 : g_attn;                 // [128,1024]
    const float* W = gsel ? W_hh0 : (W_ih0 + 1024);        // rows [N,K]
    const int ldw = gsel ? 1024 : 2048;
    const int n0 = blockIdx.x * 64;
    const int kBeg = kh * 512;

    const int tx = tid & 7;    // n-group of 8
    const int ty = tid >> 3;   // m-group of 4

    ULL acc[4][4];
#pragma unroll
    for (int i = 0; i < 4; i++)
#pragma unroll
        for (int j = 0; j < 4; j++) acc[i][j] = 0ull;

    const int arow = tid >> 1, akq = tid & 1;
    const int bn = tid >> 2, bkq = tid & 3;
    const float* Aptr = X + arow * 1024 + akq * 4;
    const float* Bptr = W + (long)(n0 + bn) * ldw + bkq * 2;

    for (int kt = kBeg; kt < kBeg + 512; kt += 8) {
        float4 a4 = *(const float4*)(Aptr + kt);
        As[akq * 4 + 0][arow] = a4.x;
        As[akq * 4 + 1][arow] = a4.y;
        As[akq * 4 + 2][arow] = a4.z;
        As[akq * 4 + 3][arow] = a4.w;
        float2 b2 = *(const float2*)(Bptr + kt);
        Bs[bkq * 2 + 0][bn] = b2.x;
        Bs[bkq * 2 + 1][bn] = b2.y;
        __syncthreads();
#pragma unroll
        for (int kk = 0; kk < 8; kk++) {
            float4 aA = *(const float4*)&As[kk][ty * 4];
            ulonglong2 b0 = *(const ulonglong2*)&Bs[kk][tx * 8];
            ulonglong2 b1 = *(const ulonglong2*)&Bs[kk][tx * 8 + 4];
            ULL ap[4];
            ap[0] = pack2(aA.x, aA.x); ap[1] = pack2(aA.y, aA.y);
            ap[2] = pack2(aA.z, aA.z); ap[3] = pack2(aA.w, aA.w);
#pragma unroll
            for (int i = 0; i < 4; i++) {
                fma2(acc[i][0], ap[i], b0.x);
                fma2(acc[i][1], ap[i], b0.y);
                fma2(acc[i][2], ap[i], b1.x);
                fma2(acc[i][3], ap[i], b1.y);
            }
        }
        __syncthreads();
    }

#pragma unroll
    for (int i = 0; i < 4; i++) {
        float* Crow = g_gates + (ty * 4 + i) * 4096 + n0 + tx * 8;
#pragma unroll
        for (int j = 0; j < 4; j++) {
            float2 vv = unpack2(acc[i][j]);
            atomicAdd(&Crow[j * 2], vv.x);
            atomicAdd(&Crow[j * 2 + 1], vv.y);
        }
    }
}

// ---------------------------------------------------------------------------
// scores[b][n] = sum_a v[a] * tanh(f_proj[b][n][a] + q[b][a])
// grid (25, 128): y = b, warp per n
// ---------------------------------------------------------------------------
__global__ __launch_bounds__(256) void energy_kernel(const float* __restrict__ v)
{
    const int b = blockIdx.y;
    const int warp = threadIdx.x >> 5, lane = threadIdx.x & 31;
    const int n = blockIdx.x * 8 + warp;
    if (n >= 196) return;

    const float* fp = g_fproj + (b * 196 + n) * 1024;
    const float* q = g_q + b * 1024;

    float acc = 0.f;
#pragma unroll
    for (int i = 0; i < 32; i += 4) {
        int k0 = lane + i * 32;
        float x0 = fp[k0] + q[k0];
        float x1 = fp[k0 + 32] + q[k0 + 32];
        float x2 = fp[k0 + 64] + q[k0 + 64];
        float x3 = fp[k0 + 96] + q[k0 + 96];
        acc = fmaf(v[k0], fast_tanh(x0), acc);
        acc = fmaf(v[k0 + 32], fast_tanh(x1), acc);
        acc = fmaf(v[k0 + 64], fast_tanh(x2), acc);
        acc = fmaf(v[k0 + 96], fast_tanh(x3), acc);
    }
#pragma unroll
    for (int o = 16; o; o >>= 1) acc += __shfl_xor_sync(0xffffffffu, acc, o);
    if (lane == 0) g_scores[b * 196 + n] = acc;
}

// ---------------------------------------------------------------------------
// softmax over n, then attn[b][f] = sum_n alpha[n] * feats[b][n][f]
// grid 128 (one per b), 512 threads
// ---------------------------------------------------------------------------
__global__ __launch_bounds__(512) void softmax_attn_kernel(const float* __restrict__ feats)
{
    const int b = blockIdx.x, tid = threadIdx.x;
    const int lane = tid & 31, warp = tid >> 5;
    __shared__ float sal[196];
    __shared__ float red[16];

    float s = (tid < 196) ? g_scores[b * 196 + tid] : -3.0e38f;

    float m = s;
#pragma unroll
    for (int o = 16; o; o >>= 1) m = fmaxf(m, __shfl_xor_sync(0xffffffffu, m, o));
    if (lane == 0) red[warp] = m;
    __syncthreads();
    if (tid == 0) {
        float t2 = red[0];
        for (int i = 1; i < 16; i++) t2 = fmaxf(t2, red[i]);
        red[0] = t2;
    }
    __syncthreads();
    const float M = red[0];
    __syncthreads();

    float e = (tid < 196) ? __expf(s - M) : 0.f;
    float sm = e;
#pragma unroll
    for (int o = 16; o; o >>= 1) sm += __shfl_xor_sync(0xffffffffu, sm, o);
    if (lane == 0) red[warp] = sm;
    __syncthreads();
    if (tid == 0) {
        float t2 = 0.f;
        for (int i = 0; i < 16; i++) t2 += red[i];
        red[0] = t2;
    }
    __syncthreads();
    const float S = red[0];
    if (tid < 196) sal[tid] = e / S;
    __syncthreads();

    const float* fb = feats + (long)b * 196 * 1024;
    float a0 = 0.f, a1 = 0.f;
#pragma unroll 4
    for (int n = 0; n < 196; n++) {
        float al = sal[n];
        a0 = fmaf(al, fb[n * 1024 + tid], a0);
        a1 = fmaf(al, fb[n * 1024 + tid + 512], a1);
    }
    g_attn[b * 1024 + tid] = a0;
    g_attn[b * 1024 + tid + 512] = a1;
}

// ---------------------------------------------------------------------------
// layer-0 LSTM cell; also records h0n/c0n into [t] slabs for batched layer 1
// ---------------------------------------------------------------------------
__global__ __launch_bounds__(256) void cell0_kernel(int t)
{
    const int idx = blockIdx.x * 256 + threadIdx.x;  // 131072
    const int b = idx >> 10, h = idx & 1023;
    const float* g = g_gates + b * 4096;
    float gi = g[h], gf = g[h + 1024], gg = g[h + 2048], go = g[h + 3072];
    float c = g_c0[idx];
    float cn = sigf(gf) * c + sigf(gi) * tanhf(gg);
    float hn = sigf(go) * tanhf(cn);
    g_c0[idx] = cn;
    g_h0[idx] = hn;
    g_c0all[t * 131072 + idx] = cn;
    g_h0all[t * 131072 + idx] = hn;
}

// ---------------------------------------------------------------------------
// layer-1 batched cell: reads g_gates1[m][*], g_c0all[m][h]; m = t*128 + b
// out[(b*32 + t)*1024 + h]
// ---------------------------------------------------------------------------
__global__ __launch_bounds__(256) void cell1_kernel(float* __restrict__ out)
{
    const int idx = blockIdx.x * 256 + threadIdx.x;  // 4194304
    const int m = idx >> 10, h = idx & 1023;
    const float* g = g_gates1 + (long)m * 4096;
    float gi = g[h], gf = g[h + 1024], gg = g[h + 2048], go = g[h + 3072];
    float c0n = g_c0all[idx];
    float c1 = sigf(gf) * c0n + sigf(gi) * tanhf(gg);
    float h1 = sigf(go) * tanhf(c1);
    const int b = m & 127, t = m >> 7;
    out[(long)(b * 32 + t) * 1024 + h] = h1;
}

// ---------------------------------------------------------------------------
// one-time folds: W1c = W_ih1 + W_hh1, b0c = b_ih0 + b_hh0, b1c = b_ih1 + b_hh1
// ---------------------------------------------------------------------------
__global__ __launch_bounds__(256) void prep_kernel(
    const float* __restrict__ W_ih1, const float* __restrict__ W_hh1,
    const float* __restrict__ b_ih0, const float* __restrict__ b_hh0,
    const float* __restrict__ b_ih1, const float* __restrict__ b_hh1)
{
    const int i = blockIdx.x * 256 + threadIdx.x;
    const int stride = gridDim.x * 256;
    for (int idx = i; idx < 4096 * 1024; idx += stride)
        g_w1c[idx] = W_ih1[idx] + W_hh1[idx];
    if (i < 4096) {
        g_b0c[i] = b_ih0[i] + b_hh0[i];
        g_b1c[i] = b_ih1[i] + b_hh1[i];
    }
}

// ---------------------------------------------------------------------------
extern "C" void kernel_launch(void* const* d_in, const int* in_sizes, int n_in,
                              void* d_out, int out_size)
{
    const float* feats = (const float*)d_in[0];
    const float* emb   = (const float*)d_in[1];
    const float* Wf    = (const float*)d_in[2];
    const float* Wh    = (const float*)d_in[3];
    const float* b_att = (const float*)d_in[4];
    const float* v     = (const float*)d_in[5];
    const float* W_ih0 = (const float*)d_in[6];
    const float* W_hh0 = (const float*)d_in[7];
    const float* b_ih0 = (const float*)d_in[8];
    const float* b_hh0 = (const float*)d_in[9];
    const float* W_ih1 = (const float*)d_in[10];
    const float* W_hh1 = (const float*)d_in[11];
    const float* b_ih1 = (const float*)d_in[12];
    const float* b_hh1 = (const float*)d_in[13];
    float* out = (float*)d_out;

    void *p_fproj, *p_pre0, *p_w1c, *p_b0c, *p_b1c;
    void *p_h0, *p_c0, *p_q, *p_gates, *p_h0all, *p_gates1;
    cudaGetSymbolAddress(&p_fproj, g_fproj);
    cudaGetSymbolAddress(&p_pre0, g_pre0);
    cudaGetSymbolAddress(&p_w1c, g_w1c);
    cudaGetSymbolAddress(&p_b0c, g_b0c);
    cudaGetSymbolAddress(&p_b1c, g_b1c);
    cudaGetSymbolAddress(&p_h0, g_h0);
    cudaGetSymbolAddress(&p_c0, g_c0);
    cudaGetSymbolAddress(&p_q, g_q);
    cudaGetSymbolAddress(&p_gates, g_gates);
    cudaGetSymbolAddress(&p_h0all, g_h0all);
    cudaGetSymbolAddress(&p_gates1, g_gates1);

    prep_kernel<<<2048, 256>>>(W_ih1, W_hh1, b_ih0, b_hh0, b_ih1, b_hh1);

    // f_proj = feats @ Wf + b_att    [25088,1024] x [1024,1024]
    gemm128_kernel<false, false, false, true><<<dim3(196, 8, 1), 256>>>(
        feats, 1024, Wf, 1024, (float*)p_fproj, 1024, b_att, 1024, 1024);

    // pre0[t][b][:] = emb[b][t][:] @ W_ih0[:, :1024]^T + (b_ih0 + b_hh0)
    gemm128_kernel<true, true, false, true><<<dim3(32, 32, 1), 256>>>(
        emb, 1024, W_ih0, 2048, (float*)p_pre0, 4096, (const float*)p_b0c, 1024, 1024);

    cudaMemsetAsync(p_h0, 0, 128 * 1024 * sizeof(float));
    cudaMemsetAsync(p_c0, 0, 128 * 1024 * sizeof(float));

    for (int t = 0; t < 32; t++) {
        // q = h0 @ Wh  (split-K=8 + atomics)
        cudaMemsetAsync(p_q, 0, 128 * 1024 * sizeof(float));
        gemm128_kernel<false, false, true, false><<<dim3(1, 8, 8), 256>>>(
            (const float*)p_h0, 1024, Wh, 1024, (float*)p_q, 1024, nullptr, 1024, 128);

        energy_kernel<<<dim3(25, 128), 256>>>(v);
        softmax_attn_kernel<<<128, 512>>>(feats);

        // gates := pre0 slice, then += attn-half + h0-half
        cudaMemcpyAsync(p_gates, (const char*)p_pre0 + (size_t)t * 128 * 4096 * 4,
                        128 * 4096 * sizeof(float), cudaMemcpyDeviceToDevice);
        gates_kernel<<<dim3(64, 1, 4), 256>>>(W_ih0, W_hh0);

        cell0_kernel<<<512, 256>>>(t);
    }

    // batched layer 1: gates1 = h0all @ (W_ih1 + W_hh1)^T + (b_ih1 + b_hh1)
    gemm128_kernel<true, false, false, true><<<dim3(32, 32, 1), 256>>>(
        (const float*)p_h0all, 1024, (const float*)p_w1c, 1024,
        (float*)p_gates1, 4096, (const float*)p_b1c, 1024, 1024);

    cell1_kernel<<<16384, 256>>>(out);
}